// round 16
// baseline (speedup 1.0000x reference)
#include <cuda_runtime.h>
#include <cuda_bf16.h>
#include <cstdint>
#include <math.h>

// Problem constants
#define BB 16
#define QQ 100
#define EE 256
#define HH 8
#define HD 32
#define SS 4096
#define NEGBIG (-1e9f)

// Scratch (device globals: allocation-free rule)
__device__ float g_Khi[(size_t)BB * SS * EE];
__device__ float g_Klo[(size_t)BB * SS * EE];
__device__ float g_Vhi[(size_t)BB * SS * EE];
__device__ float g_Vlo[(size_t)BB * SS * EE];
__device__ float g_Qp[(size_t)BB * QQ * EE];
__device__ float g_attn[(size_t)BB * QQ * EE];

#define SPLIT2 8
#define QPAD 128
#define NPART2 (BB * HH * SPLIT2 * QPAD)
__device__ float g_Pm[NPART2];
__device__ float g_Pl[NPART2];
__device__ float g_Pacc[(size_t)NPART2 * HD];

__device__ __forceinline__ uint32_t f2tf32(float f) {
    uint32_t u;
    asm("cvt.rna.tf32.f32 %0, %1;" : "=r"(u) : "f"(f));
    return u;
}
__device__ __forceinline__ void split2(float x, float& hi, float& lo) {
    uint32_t u;
    asm("cvt.rna.tf32.f32 %0, %1;" : "=r"(u) : "f"(x));
    hi = __uint_as_float(u);
    float r = x - hi;
    asm("cvt.rna.tf32.f32 %0, %1;" : "=r"(u) : "f"(r));
    lo = __uint_as_float(u);
}
__device__ __forceinline__ void mma_tf32(float c[4], const uint32_t a[4],
                                         const uint32_t b[2]) {
    asm volatile(
        "mma.sync.aligned.m16n8k8.row.col.f32.tf32.tf32.f32 "
        "{%0,%1,%2,%3}, {%4,%5,%6,%7}, {%8,%9}, {%0,%1,%2,%3};"
        : "+f"(c[0]), "+f"(c[1]), "+f"(c[2]), "+f"(c[3])
        : "r"(a[0]), "r"(a[1]), "r"(a[2]), "r"(a[3]), "r"(b[0]), "r"(b[1]));
}
__device__ __forceinline__ void mma_tf32f(float c[4], const float a[4],
                                          const float b0, const float b1) {
    uint32_t A[4] = {__float_as_uint(a[0]), __float_as_uint(a[1]),
                     __float_as_uint(a[2]), __float_as_uint(a[3])};
    uint32_t B[2] = {__float_as_uint(b0), __float_as_uint(b1)};
    mma_tf32(c, A, B);
}
__device__ __forceinline__ void cp_async16(uint32_t dst, const void* src) {
    asm volatile("cp.async.cg.shared.global [%0], [%1], 16;"
                 :: "r"(dst), "l"(src));
}
#define CP_COMMIT() asm volatile("cp.async.commit_group;" ::: "memory")

// ===========================================================================
// tf32 mma.sync GEMM (R9 config). Row-major A (+optional A2).
// Plain epilogue (C). Used for Q and O projections.
// ===========================================================================
#define MBK 16
#define SPITCH 20
__global__ __launch_bounds__(256)
void mma_gemm(const float* __restrict__ A1, const float* __restrict__ A2,
              const float* __restrict__ W, const float* __restrict__ bias,
              float* __restrict__ C, int M) {
    __shared__ uint32_t As[2][128 * SPITCH];
    __shared__ uint32_t Bs[2][128 * SPITCH];

    int tid = threadIdx.x;
    int wid = tid >> 5, lane = tid & 31;
    int bm = blockIdx.x * 128;
    int bn = blockIdx.y * 128;
    int wm = (wid & 3) * 32;
    int wn = (wid >> 2) * 64;
    int lrow = tid >> 1;
    int lkb  = (tid & 1) * 8;
    int lg = lane >> 2;
    int lk = lane & 3;

    float c[2][8][4];
    #pragma unroll
    for (int mf = 0; mf < 2; mf++)
        #pragma unroll
        for (int nf = 0; nf < 8; nf++)
            #pragma unroll
            for (int i = 0; i < 4; i++) c[mf][nf][i] = 0.f;

    float ar[8], wr[8];
    auto fetch = [&](int kt) {
        float4 a0 = make_float4(0.f, 0.f, 0.f, 0.f), a1 = a0;
        int row = bm + lrow;
        if (row < M) {
            const float* ap = A1 + (size_t)row * EE + kt * MBK + lkb;
            a0 = ((const float4*)ap)[0];
            a1 = ((const float4*)ap)[1];
            if (A2) {
                const float* pp = A2 + (size_t)row * EE + kt * MBK + lkb;
                float4 p0 = ((const float4*)pp)[0];
                float4 p1 = ((const float4*)pp)[1];
                a0.x += p0.x; a0.y += p0.y; a0.z += p0.z; a0.w += p0.w;
                a1.x += p1.x; a1.y += p1.y; a1.z += p1.z; a1.w += p1.w;
            }
        }
        const float* wp = W + (size_t)(bn + lrow) * EE + kt * MBK + lkb;
        float4 b0 = ((const float4*)wp)[0];
        float4 b1 = ((const float4*)wp)[1];
        ar[0]=a0.x; ar[1]=a0.y; ar[2]=a0.z; ar[3]=a0.w;
        ar[4]=a1.x; ar[5]=a1.y; ar[6]=a1.z; ar[7]=a1.w;
        wr[0]=b0.x; wr[1]=b0.y; wr[2]=b0.z; wr[3]=b0.w;
        wr[4]=b1.x; wr[5]=b1.y; wr[6]=b1.z; wr[7]=b1.w;
    };
    auto stage = [&](int buf) {
        uint32_t* ad = &As[buf][lrow * SPITCH + lkb];
        uint32_t* bd = &Bs[buf][lrow * SPITCH + lkb];
        #pragma unroll
        for (int i = 0; i < 8; i++) {
            ad[i] = f2tf32(ar[i]);
            bd[i] = f2tf32(wr[i]);
        }
    };

    fetch(0);
    stage(0);
    __syncthreads();

    #pragma unroll 1
    for (int kt = 0; kt < 16; kt++) {
        int buf = kt & 1;
        if (kt < 15) fetch(kt + 1);
        #pragma unroll
        for (int ks8 = 0; ks8 < 2; ks8++) {
            int kk = ks8 * 8;
            uint32_t af[2][4];
            #pragma unroll
            for (int mf = 0; mf < 2; mf++) {
                int r = wm + mf * 16 + lg;
                const uint32_t* base = &As[buf][0];
                af[mf][0] = base[r * SPITCH + kk + lk];
                af[mf][1] = base[(r + 8) * SPITCH + kk + lk];
                af[mf][2] = base[r * SPITCH + kk + lk + 4];
                af[mf][3] = base[(r + 8) * SPITCH + kk + lk + 4];
            }
            uint32_t bf[8][2];
            #pragma unroll
            for (int nf = 0; nf < 8; nf++) {
                int n = wn + nf * 8 + lg;
                bf[nf][0] = Bs[buf][n * SPITCH + kk + lk];
                bf[nf][1] = Bs[buf][n * SPITCH + kk + lk + 4];
            }
            #pragma unroll
            for (int mf = 0; mf < 2; mf++)
                #pragma unroll
                for (int nf = 0; nf < 8; nf++)
                    mma_tf32(c[mf][nf], af[mf], bf[nf]);
        }
        if (kt < 15) {
            stage(buf ^ 1);
            __syncthreads();
        }
    }

    #pragma unroll
    for (int mf = 0; mf < 2; mf++) {
        int r0 = bm + wm + mf * 16 + lg;
        #pragma unroll
        for (int nf = 0; nf < 8; nf++) {
            int cc = bn + wn + nf * 8 + lk * 2;
            float bx = bias[cc], by = bias[cc + 1];
            if (r0 < M) {
                float2 o = make_float2(c[mf][nf][0] + bx, c[mf][nf][1] + by);
                *(float2*)(C + (size_t)r0 * EE + cc) = o;
            }
            if (r0 + 8 < M) {
                float2 o = make_float2(c[mf][nf][2] + bx, c[mf][nf][3] + by);
                *(float2*)(C + (size_t)(r0 + 8) * EE + cc) = o;
            }
        }
    }
}

// ===========================================================================
// K/V projection GEMM: A read TRANSPOSED directly from image_features
// (B,E,S); epilogue SPLITS each output into tf32 hi/lo arrays (pre-split
// for attention — split2 values identical to splitting at read time).
// ===========================================================================
__global__ __launch_bounds__(256)
void mma_gemm_ti(const float* __restrict__ img, const float* __restrict__ A2,
                 const float* __restrict__ W, const float* __restrict__ bias,
                 float* __restrict__ Chi, float* __restrict__ Clo) {
    __shared__ uint32_t As[2][128 * SPITCH];
    __shared__ uint32_t Bs[2][128 * SPITCH];

    int tid = threadIdx.x;
    int wid = tid >> 5, lane = tid & 31;
    int bm = blockIdx.x * 128;
    int bn = blockIdx.y * 128;
    int wm = (wid & 3) * 32;
    int wn = (wid >> 2) * 64;
    int lrow = tid >> 1;
    int lkb  = (tid & 1) * 8;
    int lg = lane >> 2;
    int lk = lane & 3;

    int bimg = bm >> 12;          // bm / SS
    int s0   = bm & (SS - 1);

    float c[2][8][4];
    #pragma unroll
    for (int mf = 0; mf < 2; mf++)
        #pragma unroll
        for (int nf = 0; nf < 8; nf++)
            #pragma unroll
            for (int i = 0; i < 4; i++) c[mf][nf][i] = 0.f;

    float ar[8], wr[8];
    auto fetch = [&](int kt) {
        const float* ip = img + ((size_t)bimg * EE + kt * MBK + lkb) * SS
                              + s0 + lrow;
        #pragma unroll
        for (int i = 0; i < 8; i++)
            ar[i] = ip[(size_t)i * SS];
        if (A2) {
            int row = bm + lrow;
            const float* pp = A2 + (size_t)row * EE + kt * MBK + lkb;
            float4 p0 = ((const float4*)pp)[0];
            float4 p1 = ((const float4*)pp)[1];
            ar[0] += p0.x; ar[1] += p0.y; ar[2] += p0.z; ar[3] += p0.w;
            ar[4] += p1.x; ar[5] += p1.y; ar[6] += p1.z; ar[7] += p1.w;
        }
        const float* wp = W + (size_t)(bn + lrow) * EE + kt * MBK + lkb;
        float4 b0 = ((const float4*)wp)[0];
        float4 b1 = ((const float4*)wp)[1];
        wr[0]=b0.x; wr[1]=b0.y; wr[2]=b0.z; wr[3]=b0.w;
        wr[4]=b1.x; wr[5]=b1.y; wr[6]=b1.z; wr[7]=b1.w;
    };
    auto stage = [&](int buf) {
        uint32_t* ad = &As[buf][lrow * SPITCH + lkb];
        uint32_t* bd = &Bs[buf][lrow * SPITCH + lkb];
        #pragma unroll
        for (int i = 0; i < 8; i++) {
            ad[i] = f2tf32(ar[i]);
            bd[i] = f2tf32(wr[i]);
        }
    };

    fetch(0);
    stage(0);
    __syncthreads();

    #pragma unroll 1
    for (int kt = 0; kt < 16; kt++) {
        int buf = kt & 1;
        if (kt < 15) fetch(kt + 1);
        #pragma unroll
        for (int ks8 = 0; ks8 < 2; ks8++) {
            int kk = ks8 * 8;
            uint32_t af[2][4];
            #pragma unroll
            for (int mf = 0; mf < 2; mf++) {
                int r = wm + mf * 16 + lg;
                const uint32_t* base = &As[buf][0];
                af[mf][0] = base[r * SPITCH + kk + lk];
                af[mf][1] = base[(r + 8) * SPITCH + kk + lk];
                af[mf][2] = base[r * SPITCH + kk + lk + 4];
                af[mf][3] = base[(r + 8) * SPITCH + kk + lk + 4];
            }
            uint32_t bf[8][2];
            #pragma unroll
            for (int nf = 0; nf < 8; nf++) {
                int n = wn + nf * 8 + lg;
                bf[nf][0] = Bs[buf][n * SPITCH + kk + lk];
                bf[nf][1] = Bs[buf][n * SPITCH + kk + lk + 4];
            }
            #pragma unroll
            for (int mf = 0; mf < 2; mf++)
                #pragma unroll
                for (int nf = 0; nf < 8; nf++)
                    mma_tf32(c[mf][nf], af[mf], bf[nf]);
        }
        if (kt < 15) {
            stage(buf ^ 1);
            __syncthreads();
        }
    }

    // epilogue: split each output value into tf32 hi/lo, store both arrays
    #pragma unroll
    for (int mf = 0; mf < 2; mf++) {
        int r0 = bm + wm + mf * 16 + lg;
        #pragma unroll
        for (int nf = 0; nf < 8; nf++) {
            int cc = bn + wn + nf * 8 + lk * 2;
            float bx = bias[cc], by = bias[cc + 1];
            {
                float h0, l0v, h1, l1v;
                split2(c[mf][nf][0] + bx, h0, l0v);
                split2(c[mf][nf][1] + by, h1, l1v);
                *(float2*)(Chi + (size_t)r0 * EE + cc) = make_float2(h0, h1);
                *(float2*)(Clo + (size_t)r0 * EE + cc) = make_float2(l0v, l1v);
            }
            {
                float h0, l0v, h1, l1v;
                split2(c[mf][nf][2] + bx, h0, l0v);
                split2(c[mf][nf][3] + by, h1, l1v);
                *(float2*)(Chi + (size_t)(r0 + 8) * EE + cc) = make_float2(h0, h1);
                *(float2*)(Clo + (size_t)(r0 + 8) * EE + cc) = make_float2(l0v, l1v);
            }
        }
    }
}

// ===========================================================================
// Tensor-core flash attention: pre-split K/V arrays staged with cp.async
// into double-buffered dynamic smem. Dead-warp skip kept (warp 7).
// ===========================================================================
#define SC2 64
#define NCH (SS / SPLIT2 / SC2)   // 8
#define KW 2304                   // 64*36 floats
#define VW 2560                   // 64*40 floats
#define BUFW (2 * KW + 2 * VW)    // 9728 floats per buffer
#define ATTN_SMEM (2 * BUFW * 4)  // 77824 B
__global__ __launch_bounds__(256, 2)
void attn_mma(const int* __restrict__ mask) {
    extern __shared__ __align__(16) float sm[];
    int bh = blockIdx.x;
    int sp = blockIdx.y;
    int b = bh >> 3, h = bh & 7;
    int tid = threadIdx.x;
    int wid = tid >> 5, lane = tid & 31;
    int lg = lane >> 2, lk = lane & 3;
    int q0 = wid * 16;
    bool live = (q0 < QQ);       // warp-uniform

    const float scale = 0.17677669529663687f;  // 1/sqrt(32)

    float aqh[4][4], aql[4][4];
    if (live) {
        int r0c = min(q0 + lg, QQ - 1);
        int r1c = min(q0 + lg + 8, QQ - 1);
        const float* Q0 = g_Qp + ((size_t)(b * QQ + r0c)) * EE + h * HD;
        const float* Q1 = g_Qp + ((size_t)(b * QQ + r1c)) * EE + h * HD;
        #pragma unroll
        for (int ks = 0; ks < 4; ks++) {
            split2(Q0[8 * ks + lk] * scale,     aqh[ks][0], aql[ks][0]);
            split2(Q1[8 * ks + lk] * scale,     aqh[ks][1], aql[ks][1]);
            split2(Q0[8 * ks + lk + 4] * scale, aqh[ks][2], aql[ks][2]);
            split2(Q1[8 * ks + lk + 4] * scale, aqh[ks][3], aql[ks][3]);
        }
    }

    float m0 = -INFINITY, m1 = -INFINITY, l0 = 0.f, l1 = 0.f;
    float o[4][4];
    #pragma unroll
    for (int nf = 0; nf < 4; nf++)
        #pragma unroll
        for (int v = 0; v < 4; v++) o[nf][v] = 0.f;

    size_t kvoff = ((size_t)b * SS) * EE + h * HD;
    const float* Kbh = g_Khi + kvoff;
    const float* Kbl = g_Klo + kvoff;
    const float* Vbh = g_Vhi + kvoff;
    const float* Vbl = g_Vlo + kvoff;
    const int* mrow0 = mask + ((size_t)(b * QQ + min(q0 + lg, QQ - 1))) * SS;
    const int* mrow1 = mask + ((size_t)(b * QQ + min(q0 + lg + 8, QQ - 1))) * SS;

    int s00 = sp * (SS / SPLIT2);
    int ls = tid >> 2;            // loader row 0..63
    int ld0 = (tid & 3) * 8;      // loader dim offset

    uint32_t smu = (uint32_t)__cvta_generic_to_shared(sm);

    auto issue_chunk = [&](int ch) {
        int srow = s00 + ch * SC2 + ls;
        uint32_t base = smu + (uint32_t)((ch & 1) * BUFW) * 4u;
        size_t goff = (size_t)srow * EE + ld0;
        uint32_t kd = base + (uint32_t)(ls * 36 + ld0) * 4u;
        cp_async16(kd,      Kbh + goff);
        cp_async16(kd + 16, Kbh + goff + 4);
        cp_async16(kd + KW * 4,      Kbl + goff);
        cp_async16(kd + KW * 4 + 16, Kbl + goff + 4);
        uint32_t vd = base + (uint32_t)(2 * KW + ls * 40 + ld0) * 4u;
        cp_async16(vd,      Vbh + goff);
        cp_async16(vd + 16, Vbh + goff + 4);
        cp_async16(vd + VW * 4,      Vbl + goff);
        cp_async16(vd + VW * 4 + 16, Vbl + goff + 4);
        CP_COMMIT();
    };

    issue_chunk(0);

    #pragma unroll 1
    for (int ch = 0; ch < NCH; ch++) {
        int sbase = s00 + ch * SC2;
        if (ch + 1 < NCH) {
            issue_chunk(ch + 1);
            asm volatile("cp.async.wait_group 1;" ::: "memory");
        } else {
            asm volatile("cp.async.wait_group 0;" ::: "memory");
        }
        __syncthreads();

        float* Khi = sm + (ch & 1) * BUFW;
        float* Klo = Khi + KW;
        float* Vhi = Klo + KW;
        float* Vlo = Vhi + VW;

        if (live) {
            int2 mm0[8], mm1[8];
            #pragma unroll
            for (int nf = 0; nf < 8; nf++) {
                int col = sbase + 8 * nf + 2 * lk;
                mm0[nf] = *(const int2*)(mrow0 + col);
                mm1[nf] = *(const int2*)(mrow1 + col);
            }

            float c[8][4];
            #pragma unroll
            for (int nf = 0; nf < 8; nf++)
                #pragma unroll
                for (int v = 0; v < 4; v++) c[nf][v] = 0.f;
            #pragma unroll
            for (int ks = 0; ks < 4; ks++) {
                #pragma unroll
                for (int nf = 0; nf < 8; nf++) {
                    int n = 8 * nf + lg;
                    float bh0 = Khi[n * 36 + 8 * ks + lk];
                    float bh1 = Khi[n * 36 + 8 * ks + lk + 4];
                    float bl0 = Klo[n * 36 + 8 * ks + lk];
                    float bl1 = Klo[n * 36 + 8 * ks + lk + 4];
                    mma_tf32f(c[nf], aqh[ks], bh0, bh1);
                    mma_tf32f(c[nf], aqh[ks], bl0, bl1);
                    mma_tf32f(c[nf], aql[ks], bh0, bh1);
                }
            }

            float mx0 = -INFINITY, mx1 = -INFINITY;
            #pragma unroll
            for (int nf = 0; nf < 8; nf++) {
                c[nf][0] = mm0[nf].x ? c[nf][0] : NEGBIG;
                c[nf][1] = mm0[nf].y ? c[nf][1] : NEGBIG;
                c[nf][2] = mm1[nf].x ? c[nf][2] : NEGBIG;
                c[nf][3] = mm1[nf].y ? c[nf][3] : NEGBIG;
                mx0 = fmaxf(mx0, fmaxf(c[nf][0], c[nf][1]));
                mx1 = fmaxf(mx1, fmaxf(c[nf][2], c[nf][3]));
            }
            mx0 = fmaxf(mx0, __shfl_xor_sync(0xffffffffu, mx0, 1));
            mx0 = fmaxf(mx0, __shfl_xor_sync(0xffffffffu, mx0, 2));
            mx1 = fmaxf(mx1, __shfl_xor_sync(0xffffffffu, mx1, 1));
            mx1 = fmaxf(mx1, __shfl_xor_sync(0xffffffffu, mx1, 2));
            float m0n = fmaxf(m0, mx0);
            float m1n = fmaxf(m1, mx1);
            float cor0 = __expf(m0 - m0n);
            float cor1 = __expf(m1 - m1n);
            m0 = m0n; m1 = m1n;
            float s0 = 0.f, s1 = 0.f;
            #pragma unroll
            for (int nf = 0; nf < 8; nf++) {
                c[nf][0] = __expf(c[nf][0] - m0);
                c[nf][1] = __expf(c[nf][1] - m0);
                c[nf][2] = __expf(c[nf][2] - m1);
                c[nf][3] = __expf(c[nf][3] - m1);
                s0 += c[nf][0] + c[nf][1];
                s1 += c[nf][2] + c[nf][3];
            }
            s0 += __shfl_xor_sync(0xffffffffu, s0, 1);
            s0 += __shfl_xor_sync(0xffffffffu, s0, 2);
            s1 += __shfl_xor_sync(0xffffffffu, s1, 1);
            s1 += __shfl_xor_sync(0xffffffffu, s1, 2);
            l0 = l0 * cor0 + s0;
            l1 = l1 * cor1 + s1;
            #pragma unroll
            for (int nf = 0; nf < 4; nf++) {
                o[nf][0] *= cor0; o[nf][1] *= cor0;
                o[nf][2] *= cor1; o[nf][3] *= cor1;
            }

            int src0 = 4 * lg + (lk >> 1);
            int src2 = src0 + 2;
            bool odd = (lk & 1) != 0;
            #pragma unroll
            for (int ks = 0; ks < 8; ks++) {
                float t00 = __shfl_sync(0xffffffffu, c[ks][0], src0);
                float t01 = __shfl_sync(0xffffffffu, c[ks][1], src0);
                float t02 = __shfl_sync(0xffffffffu, c[ks][2], src0);
                float t03 = __shfl_sync(0xffffffffu, c[ks][3], src0);
                float t20 = __shfl_sync(0xffffffffu, c[ks][0], src2);
                float t21 = __shfl_sync(0xffffffffu, c[ks][1], src2);
                float t22 = __shfl_sync(0xffffffffu, c[ks][2], src2);
                float t23 = __shfl_sync(0xffffffffu, c[ks][3], src2);
                float a0f = odd ? t01 : t00;
                float a1f = odd ? t03 : t02;
                float a2f = odd ? t21 : t20;
                float a3f = odd ? t23 : t22;
                float ah[4], al[4];
                split2(a0f, ah[0], al[0]);
                split2(a1f, ah[1], al[1]);
                split2(a2f, ah[2], al[2]);
                split2(a3f, ah[3], al[3]);
                #pragma unroll
                for (int nf = 0; nf < 4; nf++) {
                    int n = 8 * nf + lg;
                    float bh0 = Vhi[(8 * ks + lk) * 40 + n];
                    float bh1 = Vhi[(8 * ks + lk + 4) * 40 + n];
                    float bl0 = Vlo[(8 * ks + lk) * 40 + n];
                    float bl1 = Vlo[(8 * ks + lk + 4) * 40 + n];
                    mma_tf32f(o[nf], ah, bh0, bh1);
                    mma_tf32f(o[nf], ah, bl0, bl1);
                    mma_tf32f(o[nf], al, bh0, bh1);
                }
            }
        }
        __syncthreads();   // all warps done with buf before it is re-filled
    }

    if (live) {
        size_t pbase = (size_t)(bh * SPLIT2 + sp) * QPAD;
        int r0 = q0 + lg, r1 = q0 + lg + 8;
        if (lk == 0) {
            g_Pm[pbase + r0] = m0;
            g_Pm[pbase + r1] = m1;
            g_Pl[pbase + r0] = l0;
            g_Pl[pbase + r1] = l1;
        }
        #pragma unroll
        for (int nf = 0; nf < 4; nf++) {
            int d = 8 * nf + 2 * lk;
            *(float2*)(g_Pacc + (pbase + r0) * HD + d) = make_float2(o[nf][0], o[nf][1]);
            *(float2*)(g_Pacc + (pbase + r1) * HD + d) = make_float2(o[nf][2], o[nf][3]);
        }
    }
}

// ===========================================================================
// Merge SPLIT2 partials; one warp per (b,h,q), lane = head dim.
// ===========================================================================
__global__ __launch_bounds__(256)
void attn_merge() {
    int warp = (blockIdx.x * blockDim.x + threadIdx.x) >> 5;
    int lane = threadIdx.x & 31;
    if (warp >= BB * HH * QQ) return;
    int bh = warp / QQ, q = warp % QQ;
    int b = bh >> 3, h = bh & 7;
    float M = -INFINITY;
    #pragma unroll
    for (int i = 0; i < SPLIT2; i++)
        M = fmaxf(M, g_Pm[(size_t)(bh * SPLIT2 + i) * QPAD + q]);
    float L = 0.f, ov = 0.f;
    #pragma unroll
    for (int i = 0; i < SPLIT2; i++) {
        size_t idx = (size_t)(bh * SPLIT2 + i) * QPAD + q;
        float w = __expf(g_Pm[idx] - M);
        L += g_Pl[idx] * w;
        ov += g_Pacc[idx * HD + lane] * w;
    }
    g_attn[((size_t)(b * QQ + q)) * EE + h * HD + lane] = ov / L;
}

// ===========================================================================
extern "C" void kernel_launch(void* const* d_in, const int* in_sizes, int n_in,
                              void* d_out, int out_size) {
    const float* query_features = (const float*)d_in[0];
    const float* image_features = (const float*)d_in[1];
    const int*   mask           = (const int*)d_in[2];
    const float* pos_query      = (const float*)d_in[3];
    const float* pos_image      = (const float*)d_in[4];
    const float* Wq = (const float*)d_in[5];
    const float* bq = (const float*)d_in[6];
    const float* Wk = (const float*)d_in[7];
    const float* bk = (const float*)d_in[8];
    const float* Wv = (const float*)d_in[9];
    const float* bv = (const float*)d_in[10];
    const float* Wo = (const float*)d_in[11];
    const float* bo = (const float*)d_in[12];
    float* out = (float*)d_out;

    float* Khi; cudaGetSymbolAddress((void**)&Khi, g_Khi);
    float* Klo; cudaGetSymbolAddress((void**)&Klo, g_Klo);
    float* Vhi; cudaGetSymbolAddress((void**)&Vhi, g_Vhi);
    float* Vlo; cudaGetSymbolAddress((void**)&Vlo, g_Vlo);
    float* Qp;   cudaGetSymbolAddress((void**)&Qp,   g_Qp);
    float* attn; cudaGetSymbolAddress((void**)&attn, g_attn);

    static cudaStream_t sQ = nullptr, sV = nullptr;
    static cudaEvent_t e0 = nullptr, eQ = nullptr, eV = nullptr;
    if (!sQ) {
        cudaStreamCreateWithFlags(&sQ, cudaStreamNonBlocking);
        cudaStreamCreateWithFlags(&sV, cudaStreamNonBlocking);
        cudaEventCreateWithFlags(&e0, cudaEventDisableTiming);
        cudaEventCreateWithFlags(&eQ, cudaEventDisableTiming);
        cudaEventCreateWithFlags(&eV, cudaEventDisableTiming);
        cudaFuncSetAttribute(attn_mma,
                             cudaFuncAttributeMaxDynamicSharedMemorySize,
                             ATTN_SMEM);
    }

    // fork: Q, V and K all start immediately
    cudaEventRecord(e0, 0);
    cudaStreamWaitEvent(sQ, e0, 0);
    cudaStreamWaitEvent(sV, e0, 0);
    {
        int M = BB * QQ;
        dim3 grid((M + 127) / 128, 2);
        mma_gemm<<<grid, 256, 0, sQ>>>(query_features, pos_query, Wq, bq, Qp, M);
    }
    cudaEventRecord(eQ, sQ);
    {
        dim3 grid((BB * SS) / 128, 2);
        mma_gemm_ti<<<grid, 256, 0, sV>>>(image_features, nullptr, Wv, bv,
                                          Vhi, Vlo);
    }
    cudaEventRecord(eV, sV);
    {
        dim3 grid((BB * SS) / 128, 2);
        mma_gemm_ti<<<grid, 256>>>(image_features, pos_image, Wk, bk,
                                   Khi, Klo);
    }

    // join before attention
    cudaStreamWaitEvent(0, eQ, 0);
    cudaStreamWaitEvent(0, eV, 0);

    {
        dim3 grid(BB * HH, SPLIT2);
        attn_mma<<<grid, 256, ATTN_SMEM>>>(mask);
    }
    {
        int nthreads = BB * HH * QQ * 32;
        attn_merge<<<(nthreads + 255) / 256, 256>>>();
    }
    {
        int M = BB * QQ;
        dim3 grid((M + 127) / 128, 2);
        mma_gemm<<<grid, 256>>>(attn, nullptr, Wo, bo, out, M);
    }
}

// round 17
// speedup vs baseline: 1.0524x; 1.0524x over previous
#include <cuda_runtime.h>
#include <cuda_bf16.h>
#include <cstdint>
#include <math.h>

// Problem constants
#define BB 16
#define QQ 100
#define EE 256
#define HH 8
#define HD 32
#define SS 4096
#define NEGBIG (-1e9f)

// Scratch (device globals: allocation-free rule)
__device__ float g_K[(size_t)BB * SS * EE];
__device__ float g_V[(size_t)BB * SS * EE];
__device__ float g_Qp[(size_t)BB * QQ * EE];
__device__ float g_attn[(size_t)BB * QQ * EE];

#define SPLIT2 8
#define QPAD 128
#define NPART2 (BB * HH * SPLIT2 * QPAD)
__device__ float g_Pm[NPART2];
__device__ float g_Pl[NPART2];
__device__ float g_Pacc[(size_t)NPART2 * HD];

__device__ __forceinline__ uint32_t f2tf32(float f) {
    uint32_t u;
    asm("cvt.rna.tf32.f32 %0, %1;" : "=r"(u) : "f"(f));
    return u;
}
__device__ __forceinline__ float rndtf32(float f) {
    uint32_t u;
    asm("cvt.rna.tf32.f32 %0, %1;" : "=r"(u) : "f"(f));
    return __uint_as_float(u);
}
__device__ __forceinline__ void split2(float x, float& hi, float& lo) {
    uint32_t u;
    asm("cvt.rna.tf32.f32 %0, %1;" : "=r"(u) : "f"(x));
    hi = __uint_as_float(u);
    float r = x - hi;
    asm("cvt.rna.tf32.f32 %0, %1;" : "=r"(u) : "f"(r));
    lo = __uint_as_float(u);
}
__device__ __forceinline__ void mma_tf32(float c[4], const uint32_t a[4],
                                         const uint32_t b[2]) {
    asm volatile(
        "mma.sync.aligned.m16n8k8.row.col.f32.tf32.tf32.f32 "
        "{%0,%1,%2,%3}, {%4,%5,%6,%7}, {%8,%9}, {%0,%1,%2,%3};"
        : "+f"(c[0]), "+f"(c[1]), "+f"(c[2]), "+f"(c[3])
        : "r"(a[0]), "r"(a[1]), "r"(a[2]), "r"(a[3]), "r"(b[0]), "r"(b[1]));
}
__device__ __forceinline__ void mma_tf32f(float c[4], const float a[4],
                                          const float b0, const float b1) {
    uint32_t A[4] = {__float_as_uint(a[0]), __float_as_uint(a[1]),
                     __float_as_uint(a[2]), __float_as_uint(a[3])};
    uint32_t B[2] = {__float_as_uint(b0), __float_as_uint(b1)};
    mma_tf32(c, A, B);
}

// ===========================================================================
// tf32 mma.sync GEMM (R9 config: 256 threads, warp tile 32x64, BK=16,
// SPITCH=20). Row-major A (+optional A2), used for Q and O projections.
// ===========================================================================
#define MBK 16
#define SPITCH 20
__global__ __launch_bounds__(256)
void mma_gemm(const float* __restrict__ A1, const float* __restrict__ A2,
              const float* __restrict__ W, const float* __restrict__ bias,
              float* __restrict__ C, int M) {
    __shared__ uint32_t As[2][128 * SPITCH];
    __shared__ uint32_t Bs[2][128 * SPITCH];

    int tid = threadIdx.x;
    int wid = tid >> 5, lane = tid & 31;
    int bm = blockIdx.x * 128;
    int bn = blockIdx.y * 128;
    int wm = (wid & 3) * 32;
    int wn = (wid >> 2) * 64;
    int lrow = tid >> 1;
    int lkb  = (tid & 1) * 8;
    int lg = lane >> 2;
    int lk = lane & 3;

    float c[2][8][4];
    #pragma unroll
    for (int mf = 0; mf < 2; mf++)
        #pragma unroll
        for (int nf = 0; nf < 8; nf++)
            #pragma unroll
            for (int i = 0; i < 4; i++) c[mf][nf][i] = 0.f;

    float ar[8], wr[8];
    auto fetch = [&](int kt) {
        float4 a0 = make_float4(0.f, 0.f, 0.f, 0.f), a1 = a0;
        int row = bm + lrow;
        if (row < M) {
            const float* ap = A1 + (size_t)row * EE + kt * MBK + lkb;
            a0 = ((const float4*)ap)[0];
            a1 = ((const float4*)ap)[1];
            if (A2) {
                const float* pp = A2 + (size_t)row * EE + kt * MBK + lkb;
                float4 p0 = ((const float4*)pp)[0];
                float4 p1 = ((const float4*)pp)[1];
                a0.x += p0.x; a0.y += p0.y; a0.z += p0.z; a0.w += p0.w;
                a1.x += p1.x; a1.y += p1.y; a1.z += p1.z; a1.w += p1.w;
            }
        }
        const float* wp = W + (size_t)(bn + lrow) * EE + kt * MBK + lkb;
        float4 b0 = ((const float4*)wp)[0];
        float4 b1 = ((const float4*)wp)[1];
        ar[0]=a0.x; ar[1]=a0.y; ar[2]=a0.z; ar[3]=a0.w;
        ar[4]=a1.x; ar[5]=a1.y; ar[6]=a1.z; ar[7]=a1.w;
        wr[0]=b0.x; wr[1]=b0.y; wr[2]=b0.z; wr[3]=b0.w;
        wr[4]=b1.x; wr[5]=b1.y; wr[6]=b1.z; wr[7]=b1.w;
    };
    auto stage = [&](int buf) {
        uint32_t* ad = &As[buf][lrow * SPITCH + lkb];
        uint32_t* bd = &Bs[buf][lrow * SPITCH + lkb];
        #pragma unroll
        for (int i = 0; i < 8; i++) {
            ad[i] = f2tf32(ar[i]);
            bd[i] = f2tf32(wr[i]);
        }
    };

    fetch(0);
    stage(0);
    __syncthreads();

    #pragma unroll 1
    for (int kt = 0; kt < 16; kt++) {
        int buf = kt & 1;
        if (kt < 15) fetch(kt + 1);
        #pragma unroll
        for (int ks8 = 0; ks8 < 2; ks8++) {
            int kk = ks8 * 8;
            uint32_t af[2][4];
            #pragma unroll
            for (int mf = 0; mf < 2; mf++) {
                int r = wm + mf * 16 + lg;
                const uint32_t* base = &As[buf][0];
                af[mf][0] = base[r * SPITCH + kk + lk];
                af[mf][1] = base[(r + 8) * SPITCH + kk + lk];
                af[mf][2] = base[r * SPITCH + kk + lk + 4];
                af[mf][3] = base[(r + 8) * SPITCH + kk + lk + 4];
            }
            uint32_t bf[8][2];
            #pragma unroll
            for (int nf = 0; nf < 8; nf++) {
                int n = wn + nf * 8 + lg;
                bf[nf][0] = Bs[buf][n * SPITCH + kk + lk];
                bf[nf][1] = Bs[buf][n * SPITCH + kk + lk + 4];
            }
            #pragma unroll
            for (int mf = 0; mf < 2; mf++)
                #pragma unroll
                for (int nf = 0; nf < 8; nf++)
                    mma_tf32(c[mf][nf], af[mf], bf[nf]);
        }
        if (kt < 15) {
            stage(buf ^ 1);
            __syncthreads();
        }
    }

    #pragma unroll
    for (int mf = 0; mf < 2; mf++) {
        int r0 = bm + wm + mf * 16 + lg;
        #pragma unroll
        for (int nf = 0; nf < 8; nf++) {
            int cc = bn + wn + nf * 8 + lk * 2;
            float bx = bias[cc], by = bias[cc + 1];
            if (r0 < M) {
                float2 o = make_float2(c[mf][nf][0] + bx, c[mf][nf][1] + by);
                *(float2*)(C + (size_t)r0 * EE + cc) = o;
            }
            if (r0 + 8 < M) {
                float2 o = make_float2(c[mf][nf][2] + bx, c[mf][nf][3] + by);
                *(float2*)(C + (size_t)(r0 + 8) * EE + cc) = o;
            }
        }
    }
}

// ===========================================================================
// Same GEMM, A read TRANSPOSED directly from image_features (B,E,S).
// ===========================================================================
__global__ __launch_bounds__(256)
void mma_gemm_ti(const float* __restrict__ img, const float* __restrict__ A2,
                 const float* __restrict__ W, const float* __restrict__ bias,
                 float* __restrict__ C) {
    __shared__ uint32_t As[2][128 * SPITCH];
    __shared__ uint32_t Bs[2][128 * SPITCH];

    int tid = threadIdx.x;
    int wid = tid >> 5, lane = tid & 31;
    int bm = blockIdx.x * 128;
    int bn = blockIdx.y * 128;
    int wm = (wid & 3) * 32;
    int wn = (wid >> 2) * 64;
    int lrow = tid >> 1;
    int lkb  = (tid & 1) * 8;
    int lg = lane >> 2;
    int lk = lane & 3;

    int bimg = bm >> 12;          // bm / SS
    int s0   = bm & (SS - 1);

    float c[2][8][4];
    #pragma unroll
    for (int mf = 0; mf < 2; mf++)
        #pragma unroll
        for (int nf = 0; nf < 8; nf++)
            #pragma unroll
            for (int i = 0; i < 4; i++) c[mf][nf][i] = 0.f;

    float ar[8], wr[8];
    auto fetch = [&](int kt) {
        const float* ip = img + ((size_t)bimg * EE + kt * MBK + lkb) * SS
                              + s0 + lrow;
        #pragma unroll
        for (int i = 0; i < 8; i++)
            ar[i] = ip[(size_t)i * SS];
        if (A2) {
            int row = bm + lrow;
            const float* pp = A2 + (size_t)row * EE + kt * MBK + lkb;
            float4 p0 = ((const float4*)pp)[0];
            float4 p1 = ((const float4*)pp)[1];
            ar[0] += p0.x; ar[1] += p0.y; ar[2] += p0.z; ar[3] += p0.w;
            ar[4] += p1.x; ar[5] += p1.y; ar[6] += p1.z; ar[7] += p1.w;
        }
        const float* wp = W + (size_t)(bn + lrow) * EE + kt * MBK + lkb;
        float4 b0 = ((const float4*)wp)[0];
        float4 b1 = ((const float4*)wp)[1];
        wr[0]=b0.x; wr[1]=b0.y; wr[2]=b0.z; wr[3]=b0.w;
        wr[4]=b1.x; wr[5]=b1.y; wr[6]=b1.z; wr[7]=b1.w;
    };
    auto stage = [&](int buf) {
        uint32_t* ad = &As[buf][lrow * SPITCH + lkb];
        uint32_t* bd = &Bs[buf][lrow * SPITCH + lkb];
        #pragma unroll
        for (int i = 0; i < 8; i++) {
            ad[i] = f2tf32(ar[i]);
            bd[i] = f2tf32(wr[i]);
        }
    };

    fetch(0);
    stage(0);
    __syncthreads();

    #pragma unroll 1
    for (int kt = 0; kt < 16; kt++) {
        int buf = kt & 1;
        if (kt < 15) fetch(kt + 1);
        #pragma unroll
        for (int ks8 = 0; ks8 < 2; ks8++) {
            int kk = ks8 * 8;
            uint32_t af[2][4];
            #pragma unroll
            for (int mf = 0; mf < 2; mf++) {
                int r = wm + mf * 16 + lg;
                const uint32_t* base = &As[buf][0];
                af[mf][0] = base[r * SPITCH + kk + lk];
                af[mf][1] = base[(r + 8) * SPITCH + kk + lk];
                af[mf][2] = base[r * SPITCH + kk + lk + 4];
                af[mf][3] = base[(r + 8) * SPITCH + kk + lk + 4];
            }
            uint32_t bf[8][2];
            #pragma unroll
            for (int nf = 0; nf < 8; nf++) {
                int n = wn + nf * 8 + lg;
                bf[nf][0] = Bs[buf][n * SPITCH + kk + lk];
                bf[nf][1] = Bs[buf][n * SPITCH + kk + lk + 4];
            }
            #pragma unroll
            for (int mf = 0; mf < 2; mf++)
                #pragma unroll
                for (int nf = 0; nf < 8; nf++)
                    mma_tf32(c[mf][nf], af[mf], bf[nf]);
        }
        if (kt < 15) {
            stage(buf ^ 1);
            __syncthreads();
        }
    }

    #pragma unroll
    for (int mf = 0; mf < 2; mf++) {
        int r0 = bm + wm + mf * 16 + lg;
        #pragma unroll
        for (int nf = 0; nf < 8; nf++) {
            int cc = bn + wn + nf * 8 + lk * 2;
            float bx = bias[cc], by = bias[cc + 1];
            {
                float2 o = make_float2(c[mf][nf][0] + bx, c[mf][nf][1] + by);
                *(float2*)(C + (size_t)r0 * EE + cc) = o;
            }
            {
                float2 o = make_float2(c[mf][nf][2] + bx, c[mf][nf][3] + by);
                *(float2*)(C + (size_t)(r0 + 8) * EE + cc) = o;
            }
        }
    }
}

// ===========================================================================
// Tensor-core flash attention (R14 base: static smem, reg prefetch, dead-warp
// skip). NEW: P rounded to tf32 (rna) BEFORE the l-sum; PV uses 2 MMA passes
// (P*Vhi + P*Vlo) with no P split — normalization cancels P rounding error.
// ===========================================================================
#define SC2 64
#define NCH (SS / SPLIT2 / SC2)   // 8
__global__ __launch_bounds__(256, 2)
void attn_mma(const int* __restrict__ mask) {
    int bh = blockIdx.x;
    int sp = blockIdx.y;
    int b = bh >> 3, h = bh & 7;
    int tid = threadIdx.x;
    int wid = tid >> 5, lane = tid & 31;
    int lg = lane >> 2, lk = lane & 3;
    int q0 = wid * 16;
    bool live = (q0 < QQ);       // warp-uniform

    __shared__ __align__(16) float Khi[SC2][36];
    __shared__ __align__(16) float Klo[SC2][36];
    __shared__ __align__(16) float Vhi[SC2][40];
    __shared__ __align__(16) float Vlo[SC2][40];

    const float scale = 0.17677669529663687f;  // 1/sqrt(32)

    float aqh[4][4], aql[4][4];
    if (live) {
        int r0c = min(q0 + lg, QQ - 1);
        int r1c = min(q0 + lg + 8, QQ - 1);
        const float* Q0 = g_Qp + ((size_t)(b * QQ + r0c)) * EE + h * HD;
        const float* Q1 = g_Qp + ((size_t)(b * QQ + r1c)) * EE + h * HD;
        #pragma unroll
        for (int ks = 0; ks < 4; ks++) {
            split2(Q0[8 * ks + lk] * scale,     aqh[ks][0], aql[ks][0]);
            split2(Q1[8 * ks + lk] * scale,     aqh[ks][1], aql[ks][1]);
            split2(Q0[8 * ks + lk + 4] * scale, aqh[ks][2], aql[ks][2]);
            split2(Q1[8 * ks + lk + 4] * scale, aqh[ks][3], aql[ks][3]);
        }
    }

    float m0 = -INFINITY, m1 = -INFINITY, l0 = 0.f, l1 = 0.f;
    float o[4][4];
    #pragma unroll
    for (int nf = 0; nf < 4; nf++)
        #pragma unroll
        for (int v = 0; v < 4; v++) o[nf][v] = 0.f;

    const float* Kb = g_K + ((size_t)b * SS) * EE + h * HD;
    const float* Vb = g_V + ((size_t)b * SS) * EE + h * HD;
    const int* mrow0 = mask + ((size_t)(b * QQ + min(q0 + lg, QQ - 1))) * SS;
    const int* mrow1 = mask + ((size_t)(b * QQ + min(q0 + lg + 8, QQ - 1))) * SS;

    int s00 = sp * (SS / SPLIT2);
    int ls = tid >> 2;            // loader row 0..63
    int ld0 = (tid & 3) * 8;      // loader dim offset

    float pk[8], pv[8];
    {
        const float* kp = Kb + (size_t)(s00 + ls) * EE + ld0;
        const float* vp = Vb + (size_t)(s00 + ls) * EE + ld0;
        *(float4*)&pk[0] = ((const float4*)kp)[0];
        *(float4*)&pk[4] = ((const float4*)kp)[1];
        *(float4*)&pv[0] = ((const float4*)vp)[0];
        *(float4*)&pv[4] = ((const float4*)vp)[1];
    }

    #pragma unroll 1
    for (int ch = 0; ch < NCH; ch++) {
        int sbase = s00 + ch * SC2;
        #pragma unroll
        for (int i = 0; i < 8; i++) {
            float hi, lo;
            split2(pk[i], hi, lo);
            Khi[ls][ld0 + i] = hi; Klo[ls][ld0 + i] = lo;
            split2(pv[i], hi, lo);
            Vhi[ls][ld0 + i] = hi; Vlo[ls][ld0 + i] = lo;
        }
        __syncthreads();

        if (ch + 1 < NCH) {
            const float* kp = Kb + (size_t)(sbase + SC2 + ls) * EE + ld0;
            const float* vp = Vb + (size_t)(sbase + SC2 + ls) * EE + ld0;
            *(float4*)&pk[0] = ((const float4*)kp)[0];
            *(float4*)&pk[4] = ((const float4*)kp)[1];
            *(float4*)&pv[0] = ((const float4*)vp)[0];
            *(float4*)&pv[4] = ((const float4*)vp)[1];
        }

        if (live) {
            int2 mm0[8], mm1[8];
            #pragma unroll
            for (int nf = 0; nf < 8; nf++) {
                int col = sbase + 8 * nf + 2 * lk;
                mm0[nf] = *(const int2*)(mrow0 + col);
                mm1[nf] = *(const int2*)(mrow1 + col);
            }

            float c[8][4];
            #pragma unroll
            for (int nf = 0; nf < 8; nf++)
                #pragma unroll
                for (int v = 0; v < 4; v++) c[nf][v] = 0.f;
            #pragma unroll
            for (int ks = 0; ks < 4; ks++) {
                #pragma unroll
                for (int nf = 0; nf < 8; nf++) {
                    int n = 8 * nf + lg;
                    float bh0 = Khi[n][8 * ks + lk];
                    float bh1 = Khi[n][8 * ks + lk + 4];
                    float bl0 = Klo[n][8 * ks + lk];
                    float bl1 = Klo[n][8 * ks + lk + 4];
                    mma_tf32f(c[nf], aqh[ks], bh0, bh1);
                    mma_tf32f(c[nf], aqh[ks], bl0, bl1);
                    mma_tf32f(c[nf], aql[ks], bh0, bh1);
                }
            }

            float mx0 = -INFINITY, mx1 = -INFINITY;
            #pragma unroll
            for (int nf = 0; nf < 8; nf++) {
                c[nf][0] = mm0[nf].x ? c[nf][0] : NEGBIG;
                c[nf][1] = mm0[nf].y ? c[nf][1] : NEGBIG;
                c[nf][2] = mm1[nf].x ? c[nf][2] : NEGBIG;
                c[nf][3] = mm1[nf].y ? c[nf][3] : NEGBIG;
                mx0 = fmaxf(mx0, fmaxf(c[nf][0], c[nf][1]));
                mx1 = fmaxf(mx1, fmaxf(c[nf][2], c[nf][3]));
            }
            mx0 = fmaxf(mx0, __shfl_xor_sync(0xffffffffu, mx0, 1));
            mx0 = fmaxf(mx0, __shfl_xor_sync(0xffffffffu, mx0, 2));
            mx1 = fmaxf(mx1, __shfl_xor_sync(0xffffffffu, mx1, 1));
            mx1 = fmaxf(mx1, __shfl_xor_sync(0xffffffffu, mx1, 2));
            float m0n = fmaxf(m0, mx0);
            float m1n = fmaxf(m1, mx1);
            float cor0 = __expf(m0 - m0n);
            float cor1 = __expf(m1 - m1n);
            m0 = m0n; m1 = m1n;
            // exp, then ROUND P to tf32; l-sum uses rounded P so the
            // rounding cancels under ΣP̃V/ΣP̃ normalization.
            float s0 = 0.f, s1 = 0.f;
            #pragma unroll
            for (int nf = 0; nf < 8; nf++) {
                c[nf][0] = rndtf32(__expf(c[nf][0] - m0));
                c[nf][1] = rndtf32(__expf(c[nf][1] - m0));
                c[nf][2] = rndtf32(__expf(c[nf][2] - m1));
                c[nf][3] = rndtf32(__expf(c[nf][3] - m1));
                s0 += c[nf][0] + c[nf][1];
                s1 += c[nf][2] + c[nf][3];
            }
            s0 += __shfl_xor_sync(0xffffffffu, s0, 1);
            s0 += __shfl_xor_sync(0xffffffffu, s0, 2);
            s1 += __shfl_xor_sync(0xffffffffu, s1, 1);
            s1 += __shfl_xor_sync(0xffffffffu, s1, 2);
            l0 = l0 * cor0 + s0;
            l1 = l1 * cor1 + s1;
            #pragma unroll
            for (int nf = 0; nf < 4; nf++) {
                o[nf][0] *= cor0; o[nf][1] *= cor0;
                o[nf][2] *= cor1; o[nf][3] *= cor1;
            }

            // ---- O += P V (2-pass: P*Vhi + P*Vlo); P already tf32 ----
            int src0 = 4 * lg + (lk >> 1);
            int src2 = src0 + 2;
            bool odd = (lk & 1) != 0;
            #pragma unroll
            for (int ks = 0; ks < 8; ks++) {
                float t00 = __shfl_sync(0xffffffffu, c[ks][0], src0);
                float t01 = __shfl_sync(0xffffffffu, c[ks][1], src0);
                float t02 = __shfl_sync(0xffffffffu, c[ks][2], src0);
                float t03 = __shfl_sync(0xffffffffu, c[ks][3], src0);
                float t20 = __shfl_sync(0xffffffffu, c[ks][0], src2);
                float t21 = __shfl_sync(0xffffffffu, c[ks][1], src2);
                float t22 = __shfl_sync(0xffffffffu, c[ks][2], src2);
                float t23 = __shfl_sync(0xffffffffu, c[ks][3], src2);
                float ap[4];
                ap[0] = odd ? t01 : t00;
                ap[1] = odd ? t03 : t02;
                ap[2] = odd ? t21 : t20;
                ap[3] = odd ? t23 : t22;
                #pragma unroll
                for (int nf = 0; nf < 4; nf++) {
                    int n = 8 * nf + lg;
                    float bh0 = Vhi[8 * ks + lk][n];
                    float bh1 = Vhi[8 * ks + lk + 4][n];
                    float bl0 = Vlo[8 * ks + lk][n];
                    float bl1 = Vlo[8 * ks + lk + 4][n];
                    mma_tf32f(o[nf], ap, bh0, bh1);
                    mma_tf32f(o[nf], ap, bl0, bl1);
                }
            }
        }
        __syncthreads();
    }

    if (live) {
        size_t pbase = (size_t)(bh * SPLIT2 + sp) * QPAD;
        int r0 = q0 + lg, r1 = q0 + lg + 8;
        if (lk == 0) {
            g_Pm[pbase + r0] = m0;
            g_Pm[pbase + r1] = m1;
            g_Pl[pbase + r0] = l0;
            g_Pl[pbase + r1] = l1;
        }
        #pragma unroll
        for (int nf = 0; nf < 4; nf++) {
            int d = 8 * nf + 2 * lk;
            *(float2*)(g_Pacc + (pbase + r0) * HD + d) = make_float2(o[nf][0], o[nf][1]);
            *(float2*)(g_Pacc + (pbase + r1) * HD + d) = make_float2(o[nf][2], o[nf][3]);
        }
    }
}

// ===========================================================================
// Merge SPLIT2 partials; one warp per (b,h,q), lane = head dim.
// ===========================================================================
__global__ __launch_bounds__(256)
void attn_merge() {
    int warp = (blockIdx.x * blockDim.x + threadIdx.x) >> 5;
    int lane = threadIdx.x & 31;
    if (warp >= BB * HH * QQ) return;
    int bh = warp / QQ, q = warp % QQ;
    int b = bh >> 3, h = bh & 7;
    float M = -INFINITY;
    #pragma unroll
    for (int i = 0; i < SPLIT2; i++)
        M = fmaxf(M, g_Pm[(size_t)(bh * SPLIT2 + i) * QPAD + q]);
    float L = 0.f, ov = 0.f;
    #pragma unroll
    for (int i = 0; i < SPLIT2; i++) {
        size_t idx = (size_t)(bh * SPLIT2 + i) * QPAD + q;
        float w = __expf(g_Pm[idx] - M);
        L += g_Pl[idx] * w;
        ov += g_Pacc[idx * HD + lane] * w;
    }
    g_attn[((size_t)(b * QQ + q)) * EE + h * HD + lane] = ov / L;
}

// ===========================================================================
extern "C" void kernel_launch(void* const* d_in, const int* in_sizes, int n_in,
                              void* d_out, int out_size) {
    const float* query_features = (const float*)d_in[0];
    const float* image_features = (const float*)d_in[1];
    const int*   mask           = (const int*)d_in[2];
    const float* pos_query      = (const float*)d_in[3];
    const float* pos_image      = (const float*)d_in[4];
    const float* Wq = (const float*)d_in[5];
    const float* bq = (const float*)d_in[6];
    const float* Wk = (const float*)d_in[7];
    const float* bk = (const float*)d_in[8];
    const float* Wv = (const float*)d_in[9];
    const float* bv = (const float*)d_in[10];
    const float* Wo = (const float*)d_in[11];
    const float* bo = (const float*)d_in[12];
    float* out = (float*)d_out;

    float* Kp;   cudaGetSymbolAddress((void**)&Kp,   g_K);
    float* Vp;   cudaGetSymbolAddress((void**)&Vp,   g_V);
    float* Qp;   cudaGetSymbolAddress((void**)&Qp,   g_Qp);
    float* attn; cudaGetSymbolAddress((void**)&attn, g_attn);

    static cudaStream_t sQ = nullptr, sV = nullptr;
    static cudaEvent_t e0 = nullptr, eQ = nullptr, eV = nullptr;
    if (!sQ) {
        cudaStreamCreateWithFlags(&sQ, cudaStreamNonBlocking);
        cudaStreamCreateWithFlags(&sV, cudaStreamNonBlocking);
        cudaEventCreateWithFlags(&e0, cudaEventDisableTiming);
        cudaEventCreateWithFlags(&eQ, cudaEventDisableTiming);
        cudaEventCreateWithFlags(&eV, cudaEventDisableTiming);
    }

    // fork: Q, V and K all start immediately
    cudaEventRecord(e0, 0);
    cudaStreamWaitEvent(sQ, e0, 0);
    cudaStreamWaitEvent(sV, e0, 0);
    {
        int M = BB * QQ;
        dim3 grid((M + 127) / 128, 2);
        mma_gemm<<<grid, 256, 0, sQ>>>(query_features, pos_query, Wq, bq, Qp, M);
    }
    cudaEventRecord(eQ, sQ);
    {
        dim3 grid((BB * SS) / 128, 2);
        mma_gemm_ti<<<grid, 256, 0, sV>>>(image_features, nullptr, Wv, bv, Vp);
    }
    cudaEventRecord(eV, sV);
    {
        dim3 grid((BB * SS) / 128, 2);
        mma_gemm_ti<<<grid, 256>>>(image_features, pos_image, Wk, bk, Kp);
    }

    // join before attention
    cudaStreamWaitEvent(0, eQ, 0);
    cudaStreamWaitEvent(0, eV, 0);

    {
        dim3 grid(BB * HH, SPLIT2);
        attn_mma<<<grid, 256>>>(mask);
    }
    {
        int nthreads = BB * HH * QQ * 32;
        attn_merge<<<(nthreads + 255) / 256, 256>>>();
    }
    {
        int M = BB * QQ;
        dim3 grid((M + 127) / 128, 2);
        mma_gemm<<<grid, 256>>>(attn, nullptr, Wo, bo, out, M);
    }
}